// round 3
// baseline (speedup 1.0000x reference)
#include <cuda_runtime.h>
#include <cstdint>

#define BB 32
#define NN 4096
#define DD 768
#define KK 1024
#define ROWS_PER_BLK 16

typedef unsigned long long u64;

__device__ int g_topk[BB * KK];

// Map float to uint with ascending unsigned order == ascending float order.
__device__ __forceinline__ unsigned f2ord(float f) {
    unsigned u = __float_as_uint(f);
    return (u & 0x80000000u) ? ~u : (u | 0x80000000u);
}

__device__ __forceinline__ void cswap(u64& a, u64& b, bool desc) {
    // a sits at the lower global index of the pair
    bool sw = desc ? (a < b) : (a > b);
    if (sw) { u64 t = a; a = b; b = t; }
}

// Register-blocked bitonic sort of 4096 composite keys, descending.
// key = (ord(val) << 12) | (4095 - idx)  => order = (value desc, index asc),
// matching jax.lax.top_k.
// 512 threads, thread t owns global indices i = 8t .. 8t+7 in registers.
//   j in {1,2,4}    : in-register compare-exchange      (33 stages)
//   j in {8..128}   : warp shfl_xor, lane mask j/8      (35 stages)
//   j in {256..2048}: smem exchange + __syncthreads     (10 stages)
__global__ __launch_bounds__(512) void topk_sort_kernel(const float* __restrict__ sig) {
    __shared__ u64 sm[NN];
    const int t  = threadIdx.x;
    const int b  = blockIdx.x;
    const int i0 = 8 * t;

    u64 r[8];
    {
        const float4* p = (const float4*)(sig + (size_t)b * NN);
        float4 v0 = p[2 * t + 0];
        float4 v1 = p[2 * t + 1];
        r[0] = ((u64)f2ord(v0.x) << 12) | (u64)(4095 - (i0 + 0));
        r[1] = ((u64)f2ord(v0.y) << 12) | (u64)(4095 - (i0 + 1));
        r[2] = ((u64)f2ord(v0.z) << 12) | (u64)(4095 - (i0 + 2));
        r[3] = ((u64)f2ord(v0.w) << 12) | (u64)(4095 - (i0 + 3));
        r[4] = ((u64)f2ord(v1.x) << 12) | (u64)(4095 - (i0 + 4));
        r[5] = ((u64)f2ord(v1.y) << 12) | (u64)(4095 - (i0 + 5));
        r[6] = ((u64)f2ord(v1.z) << 12) | (u64)(4095 - (i0 + 6));
        r[7] = ((u64)f2ord(v1.w) << 12) | (u64)(4095 - (i0 + 7));
    }

    for (int k = 2; k <= NN; k <<= 1) {
        for (int j = k >> 1; j > 0; j >>= 1) {
            if (j >= 256) {
                __syncthreads();                 // prior smem reads complete
                #pragma unroll
                for (int e = 0; e < 8; e++) sm[i0 + e] = r[e];
                __syncthreads();
                // k >= 512, j >= 256: direction/lower uniform across e
                bool desc     = ((i0 & k) == 0);
                bool lower    = ((i0 & j) == 0);
                bool keep_max = (desc == lower);
                #pragma unroll
                for (int e = 0; e < 8; e++) {
                    u64 o = sm[(i0 + e) ^ j];
                    r[e] = keep_max ? (r[e] > o ? r[e] : o)
                                    : (r[e] < o ? r[e] : o);
                }
            } else if (j >= 8) {
                int  m        = j >> 3;          // lane xor mask, 1..16
                bool desc     = ((i0 & k) == 0); // k >= 16: uniform across e
                bool lower    = ((t & m) == 0);
                bool keep_max = (desc == lower);
                #pragma unroll
                for (int e = 0; e < 8; e++) {
                    u64 o = __shfl_xor_sync(0xffffffffu, r[e], m);
                    r[e] = keep_max ? (r[e] > o ? r[e] : o)
                                    : (r[e] < o ? r[e] : o);
                }
            } else {
                // j in {1,2,4}: in-register pairs (e, e|j)
                #pragma unroll
                for (int e = 0; e < 8; e++) {
                    if ((e & j) == 0) {
                        bool desc = (((i0 + e) & k) == 0);
                        cswap(r[e], r[e | j], desc);
                    }
                }
            }
        }
    }

    if (t < KK / 8) {
        #pragma unroll
        for (int e = 0; e < 8; e++)
            g_topk[b * KK + i0 + e] = 4095 - (int)(r[e] & 0xFFFu);
    }
}

// Gather: 16 rows per CTA, 192 threads (one float4 column each), MLP=16.
__global__ __launch_bounds__(192) void gather_kernel(const float4* __restrict__ x,
                                                     float4* __restrict__ out) {
    const int base = blockIdx.x * ROWS_PER_BLK;
    const int tid  = threadIdx.x;

    float4 vals[ROWS_PER_BLK];
    #pragma unroll
    for (int r = 0; r < ROWS_PER_BLK; r++) {
        int row = base + r;
        int b   = row / (KK + 1);
        int rr  = row - b * (KK + 1);
        int src_row = (rr == 0) ? 0 : (1 + __ldg(&g_topk[b * KK + rr - 1]));
        vals[r] = __ldcs(x + ((size_t)b * (NN + 1) + (size_t)src_row) * (DD / 4) + tid);
    }

    #pragma unroll
    for (int r = 0; r < ROWS_PER_BLK; r++)
        __stcs(out + (size_t)(base + r) * (DD / 4) + tid, vals[r]);
}

extern "C" void kernel_launch(void* const* d_in, const int* in_sizes, int n_in,
                              void* d_out, int out_size) {
    const float* x   = (const float*)d_in[0];   // [B, N+1, D] fp32
    const float* sig = (const float*)d_in[1];   // [B, N] fp32
    (void)in_sizes; (void)n_in; (void)out_size;

    topk_sort_kernel<<<BB, 512>>>(sig);
    gather_kernel<<<BB * (KK + 1) / ROWS_PER_BLK, 192>>>((const float4*)x, (float4*)d_out);
}

// round 4
// speedup vs baseline: 1.8480x; 1.8480x over previous
#include <cuda_runtime.h>
#include <cstdint>

#define BB 32
#define NN 4096
#define DD 768
#define KK 1024
#define CHUNK 1024
#define NCHUNK 4
#define ROWS_PER_BLK 8

typedef unsigned long long u64;

__device__ int g_topk[BB * KK];
__device__ u64 g_scratch[BB * NN];   // per-batch: 4 sorted descending chunks

// Map float to uint with ascending unsigned order == ascending float order.
__device__ __forceinline__ unsigned f2ord(float f) {
    unsigned u = __float_as_uint(f);
    return (u & 0x80000000u) ? ~u : (u | 0x80000000u);
}

__device__ __forceinline__ void cswap(u64& a, u64& b, bool desc) {
    bool sw = desc ? (a < b) : (a > b);
    if (sw) { u64 t = a; a = b; b = t; }
}

// ---------------------------------------------------------------------------
// Kernel A: 128 CTAs. CTA (b, c) sorts chunk c (1024 keys) of batch b,
// descending by composite key (ord << 12) | (4095 - global_idx), which gives
// jax.lax.top_k order: value desc, index asc on ties.
// 256 threads x 4 keys: j in {1,2} registers, j in {4..64} shfl,
// j in {128,256,512} smem (6 stages of 55 touch smem).
// ---------------------------------------------------------------------------
__global__ __launch_bounds__(256) void sort_chunk_kernel(const float* __restrict__ sig) {
    __shared__ u64 sm[CHUNK];
    const int cta = blockIdx.x;
    const int b   = cta >> 2;
    const int c   = cta & 3;
    const int t   = threadIdx.x;
    const int i0  = 4 * t;

    u64 r[4];
    {
        float4 v = ((const float4*)(sig + (size_t)b * NN + (size_t)c * CHUNK))[t];
        int g = c * CHUNK + i0;
        r[0] = ((u64)f2ord(v.x) << 12) | (u64)(4095 - (g + 0));
        r[1] = ((u64)f2ord(v.y) << 12) | (u64)(4095 - (g + 1));
        r[2] = ((u64)f2ord(v.z) << 12) | (u64)(4095 - (g + 2));
        r[3] = ((u64)f2ord(v.w) << 12) | (u64)(4095 - (g + 3));
    }

    for (int k = 2; k <= CHUNK; k <<= 1) {
        for (int j = k >> 1; j > 0; j >>= 1) {
            if (j >= 128) {
                __syncthreads();
                #pragma unroll
                for (int e = 0; e < 4; e++) sm[i0 + e] = r[e];
                __syncthreads();
                bool desc     = ((i0 & k) == 0);   // k>=256: uniform over e
                bool lower    = ((i0 & j) == 0);
                bool keep_max = (desc == lower);
                #pragma unroll
                for (int e = 0; e < 4; e++) {
                    u64 o = sm[(i0 + e) ^ j];
                    r[e] = keep_max ? (r[e] > o ? r[e] : o)
                                    : (r[e] < o ? r[e] : o);
                }
            } else if (j >= 4) {
                int  m        = j >> 2;            // lane xor mask 1..16
                bool desc     = ((i0 & k) == 0);   // k>=8: uniform over e
                bool lower    = ((t & m) == 0);
                bool keep_max = (desc == lower);
                #pragma unroll
                for (int e = 0; e < 4; e++) {
                    u64 o = __shfl_xor_sync(0xffffffffu, r[e], m);
                    r[e] = keep_max ? (r[e] > o ? r[e] : o)
                                    : (r[e] < o ? r[e] : o);
                }
            } else if (j == 2) {
                cswap(r[0], r[2], ((i0 + 0) & k) == 0);
                cswap(r[1], r[3], ((i0 + 1) & k) == 0);
            } else {  // j == 1
                cswap(r[0], r[1], ((i0 + 0) & k) == 0);
                cswap(r[2], r[3], ((i0 + 2) & k) == 0);
            }
        }
    }

    u64* dst = g_scratch + (size_t)b * NN + (size_t)c * CHUNK + i0;
    #pragma unroll
    for (int e = 0; e < 4; e++) dst[e] = r[e];
}

// ---------------------------------------------------------------------------
// Kernel B: 32 CTAs, one per batch. Merge 4 sorted descending 1024-lists into
// the descending top-1024 using bitonic partial merges:
//   L[i] = max(A[i], B[1023-i]) holds top-1024 of A∪B and is bitonic;
//   10 descending merge stages (keep max at lower index) sort it.
// ---------------------------------------------------------------------------
__global__ __launch_bounds__(256) void merge_topk_kernel() {
    __shared__ u64 s[NN];
    const int b = blockIdx.x;
    const int t = threadIdx.x;

    const u64* src = g_scratch + (size_t)b * NN;
    #pragma unroll
    for (int i = t; i < NN; i += 256) s[i] = src[i];
    __syncthreads();

    // Round 1: M0[i] = max(L0[i], L1[1023-i]) -> s[0..1023]
    //          M1[i] = max(L2[i], L3[1023-i]) -> s[2048..3071]
    // (each output cell is read only by its own writer; other operand regions
    //  are never written in this phase)
    #pragma unroll
    for (int q = 0; q < 4; q++) {
        int i = t + 256 * q;
        u64 a0 = s[i],        b0 = s[2047 - i];
        u64 a1 = s[2048 + i], b1 = s[4095 - i];
        s[i]        = a0 > b0 ? a0 : b0;
        s[2048 + i] = a1 > b1 ? a1 : b1;
    }
    __syncthreads();

    // 10 descending bitonic merge stages on M0 and M1 simultaneously.
    for (int j = 512; j >= 1; j >>= 1) {
        #pragma unroll
        for (int q = 0; q < 4; q++) {
            int p    = t + 256 * q;          // pair id 0..1023
            int arr  = p >> 9;               // 0 -> M0, 1 -> M1
            int pp   = p & 511;
            int i    = ((pp & ~(j - 1)) << 1) | (pp & (j - 1));
            int base = arr ? 2048 : 0;
            u64 a = s[base + i];
            u64 c = s[base + i + j];
            s[base + i]     = a > c ? a : c;
            s[base + i + j] = a > c ? c : a;
        }
        __syncthreads();
    }

    // Round 2: F[i] = max(M0[i], M1[1023-i]) -> s[0..1023]
    #pragma unroll
    for (int q = 0; q < 4; q++) {
        int i = t + 256 * q;
        u64 a = s[i], c = s[3071 - i];
        s[i] = a > c ? a : c;
    }
    __syncthreads();

    for (int j = 512; j >= 1; j >>= 1) {
        #pragma unroll
        for (int q = 0; q < 2; q++) {
            int p = t + 256 * q;             // pair id 0..511
            int i = ((p & ~(j - 1)) << 1) | (p & (j - 1));
            u64 a = s[i];
            u64 c = s[i + j];
            s[i]     = a > c ? a : c;
            s[i + j] = a > c ? c : a;
        }
        __syncthreads();
    }

    #pragma unroll
    for (int q = 0; q < 4; q++) {
        int i = t + 256 * q;
        g_topk[b * KK + i] = 4095 - (int)(s[i] & 0xFFFu);
    }
}

// ---------------------------------------------------------------------------
// Gather: 8 rows per CTA, 192 threads (one float4 column each), MLP=8.
// (round-2 config: measured 27.8us, 5.2 TB/s)
// ---------------------------------------------------------------------------
__global__ __launch_bounds__(192) void gather_kernel(const float4* __restrict__ x,
                                                     float4* __restrict__ out) {
    const int base = blockIdx.x * ROWS_PER_BLK;
    const int tid  = threadIdx.x;

    const float4* srcs[ROWS_PER_BLK];
    #pragma unroll
    for (int r = 0; r < ROWS_PER_BLK; r++) {
        int row = base + r;
        int b   = row / (KK + 1);
        int rr  = row - b * (KK + 1);
        int src_row = (rr == 0) ? 0 : (1 + g_topk[b * KK + rr - 1]);
        srcs[r] = x + ((size_t)b * (NN + 1) + (size_t)src_row) * (DD / 4);
    }

    float4 vals[ROWS_PER_BLK];
    #pragma unroll
    for (int r = 0; r < ROWS_PER_BLK; r++)
        vals[r] = __ldcs(srcs[r] + tid);

    #pragma unroll
    for (int r = 0; r < ROWS_PER_BLK; r++)
        out[(size_t)(base + r) * (DD / 4) + tid] = vals[r];
}

extern "C" void kernel_launch(void* const* d_in, const int* in_sizes, int n_in,
                              void* d_out, int out_size) {
    const float* x   = (const float*)d_in[0];   // [B, N+1, D] fp32
    const float* sig = (const float*)d_in[1];   // [B, N] fp32
    (void)in_sizes; (void)n_in; (void)out_size;

    sort_chunk_kernel<<<BB * NCHUNK, 256>>>(sig);
    merge_topk_kernel<<<BB, 256>>>();
    gather_kernel<<<BB * (KK + 1) / ROWS_PER_BLK, 192>>>((const float4*)x, (float4*)d_out);
}

// round 5
// speedup vs baseline: 1.9348x; 1.0470x over previous
#include <cuda_runtime.h>
#include <cstdint>

#define BB 32
#define NN 4096
#define DD 768
#define KK 1024
#define CHUNK 1024
#define NCHUNK 4
#define ROWS_PER_BLK 8

typedef unsigned long long u64;

__device__ int g_topk[BB * KK];
__device__ u64 g_scratch[BB * NN];   // per-batch: 4 sorted descending chunks

// Map float to uint with ascending unsigned order == ascending float order.
__device__ __forceinline__ unsigned f2ord(float f) {
    unsigned u = __float_as_uint(f);
    return (u & 0x80000000u) ? ~u : (u | 0x80000000u);
}

__device__ __forceinline__ void cswap(u64& a, u64& b, bool desc) {
    bool sw = desc ? (a < b) : (a > b);
    if (sw) { u64 t = a; a = b; b = t; }
}

// ---------------------------------------------------------------------------
// Kernel A (unchanged from round 4, measured 13.8us): CTA (b,c) sorts chunk c
// of batch b descending by key (ord << 12) | (4095 - global_idx)
// => jax.lax.top_k order (value desc, index asc). Keys are strictly distinct.
// ---------------------------------------------------------------------------
__global__ __launch_bounds__(256) void sort_chunk_kernel(const float* __restrict__ sig) {
    __shared__ u64 sm[CHUNK];
    const int cta = blockIdx.x;
    const int b   = cta >> 2;
    const int c   = cta & 3;
    const int t   = threadIdx.x;
    const int i0  = 4 * t;

    u64 r[4];
    {
        float4 v = ((const float4*)(sig + (size_t)b * NN + (size_t)c * CHUNK))[t];
        int g = c * CHUNK + i0;
        r[0] = ((u64)f2ord(v.x) << 12) | (u64)(4095 - (g + 0));
        r[1] = ((u64)f2ord(v.y) << 12) | (u64)(4095 - (g + 1));
        r[2] = ((u64)f2ord(v.z) << 12) | (u64)(4095 - (g + 2));
        r[3] = ((u64)f2ord(v.w) << 12) | (u64)(4095 - (g + 3));
    }

    for (int k = 2; k <= CHUNK; k <<= 1) {
        for (int j = k >> 1; j > 0; j >>= 1) {
            if (j >= 128) {
                __syncthreads();
                #pragma unroll
                for (int e = 0; e < 4; e++) sm[i0 + e] = r[e];
                __syncthreads();
                bool desc     = ((i0 & k) == 0);
                bool lower    = ((i0 & j) == 0);
                bool keep_max = (desc == lower);
                #pragma unroll
                for (int e = 0; e < 4; e++) {
                    u64 o = sm[(i0 + e) ^ j];
                    r[e] = keep_max ? (r[e] > o ? r[e] : o)
                                    : (r[e] < o ? r[e] : o);
                }
            } else if (j >= 4) {
                int  m        = j >> 2;
                bool desc     = ((i0 & k) == 0);
                bool lower    = ((t & m) == 0);
                bool keep_max = (desc == lower);
                #pragma unroll
                for (int e = 0; e < 4; e++) {
                    u64 o = __shfl_xor_sync(0xffffffffu, r[e], m);
                    r[e] = keep_max ? (r[e] > o ? r[e] : o)
                                    : (r[e] < o ? r[e] : o);
                }
            } else if (j == 2) {
                cswap(r[0], r[2], ((i0 + 0) & k) == 0);
                cswap(r[1], r[3], ((i0 + 1) & k) == 0);
            } else {
                cswap(r[0], r[1], ((i0 + 0) & k) == 0);
                cswap(r[2], r[3], ((i0 + 2) & k) == 0);
            }
        }
    }

    u64* dst = g_scratch + (size_t)b * NN + (size_t)c * CHUNK + i0;
    #pragma unroll
    for (int e = 0; e < 4; e++) dst[e] = r[e];
}

// ---------------------------------------------------------------------------
// Kernel B: rank-based merge. CTA (b, c): each of 1024 threads owns element t
// of sorted chunk c. Its final rank among all 4096 = t + sum over the other 3
// chunks of (# elements strictly greater), each found by a 10-step binary
// search in smem. All keys distinct => ranks are a permutation of 0..4095.
// Write idx to g_topk[rank] iff rank < 1024. 128 CTAs x 1024 thr, no barriers
// in the search phase, 3-way ILP across independent searches.
// ---------------------------------------------------------------------------
__global__ __launch_bounds__(1024) void rank_merge_kernel() {
    __shared__ u64 sm[3 * CHUNK];    // the other 3 sorted chunks
    const int b = blockIdx.x >> 2;
    const int c = blockIdx.x & 3;
    const int t = threadIdx.x;

    const u64* base = g_scratch + (size_t)b * NN;

    // Load the 3 other chunks into smem (coalesced).
    #pragma unroll
    for (int o = 0; o < 3; o++) {
        int oc = o + (o >= c ? 1 : 0);
        sm[o * CHUNK + t] = base[oc * CHUNK + t];
    }

    u64 key = base[c * CHUNK + t];
    __syncthreads();

    // 3 interleaved branchless binary searches: cnt_o = #{x in chunk_o : x > key}
    int c0 = 0, c1 = 0, c2 = 0;
    #pragma unroll
    for (int s = 512; s >= 1; s >>= 1) {
        if (sm[0 * CHUNK + c0 + s - 1] > key) c0 += s;
        if (sm[1 * CHUNK + c1 + s - 1] > key) c1 += s;
        if (sm[2 * CHUNK + c2 + s - 1] > key) c2 += s;
    }

    int rank = t + c0 + c1 + c2;
    if (rank < KK)
        g_topk[b * KK + rank] = 4095 - (int)(key & 0xFFFu);
}

// ---------------------------------------------------------------------------
// Gather (unchanged round-2 config, measured 27.8us): 8 rows/CTA, 192 threads.
// ---------------------------------------------------------------------------
__global__ __launch_bounds__(192) void gather_kernel(const float4* __restrict__ x,
                                                     float4* __restrict__ out) {
    const int base = blockIdx.x * ROWS_PER_BLK;
    const int tid  = threadIdx.x;

    const float4* srcs[ROWS_PER_BLK];
    #pragma unroll
    for (int r = 0; r < ROWS_PER_BLK; r++) {
        int row = base + r;
        int b   = row / (KK + 1);
        int rr  = row - b * (KK + 1);
        int src_row = (rr == 0) ? 0 : (1 + g_topk[b * KK + rr - 1]);
        srcs[r] = x + ((size_t)b * (NN + 1) + (size_t)src_row) * (DD / 4);
    }

    float4 vals[ROWS_PER_BLK];
    #pragma unroll
    for (int r = 0; r < ROWS_PER_BLK; r++)
        vals[r] = __ldcs(srcs[r] + tid);

    #pragma unroll
    for (int r = 0; r < ROWS_PER_BLK; r++)
        out[(size_t)(base + r) * (DD / 4) + tid] = vals[r];
}

extern "C" void kernel_launch(void* const* d_in, const int* in_sizes, int n_in,
                              void* d_out, int out_size) {
    const float* x   = (const float*)d_in[0];   // [B, N+1, D] fp32
    const float* sig = (const float*)d_in[1];   // [B, N] fp32
    (void)in_sizes; (void)n_in; (void)out_size;

    sort_chunk_kernel<<<BB * NCHUNK, 256>>>(sig);
    rank_merge_kernel<<<BB * NCHUNK, 1024>>>();
    gather_kernel<<<BB * (KK + 1) / ROWS_PER_BLK, 192>>>((const float4*)x, (float4*)d_out);
}

// round 6
// speedup vs baseline: 2.0343x; 1.0514x over previous
#include <cuda_runtime.h>
#include <cstdint>

#define BB 32
#define NN 4096
#define DD 768
#define KK 1024
#define CHUNK 1024
#define NCHUNK 4
#define ROWS_PER_BLK 8

typedef unsigned long long u64;

__device__ int g_topk[BB * KK];
__device__ u64 g_scratch[BB * NN];   // per-batch: 4 sorted descending chunks

// Map float to uint with ascending unsigned order == ascending float order.
__device__ __forceinline__ unsigned f2ord(float f) {
    unsigned u = __float_as_uint(f);
    return (u & 0x80000000u) ? ~u : (u | 0x80000000u);
}

__device__ __forceinline__ void cswap(u64& a, u64& b, bool desc) {
    bool sw = desc ? (a < b) : (a > b);
    if (sw) { u64 t = a; a = b; b = t; }
}

// ---------------------------------------------------------------------------
// Kernel A: CTA (b,c) sorts chunk c of batch b descending by composite key
// (ord << 12) | (4095 - global_idx)  => jax.lax.top_k order (value desc,
// index asc). Keys strictly distinct. 256 threads x 4 keys.
// ALL 55 stages fully unrolled: k and j are compile-time constants, so the
// per-stage branch ladder / mask math constant-folds to straight-line code.
// ---------------------------------------------------------------------------
__global__ __launch_bounds__(256) void sort_chunk_kernel(const float* __restrict__ sig) {
    __shared__ u64 sm[CHUNK];
    const int cta = blockIdx.x;
    const int b   = cta >> 2;
    const int c   = cta & 3;
    const int t   = threadIdx.x;
    const int i0  = 4 * t;

    u64 r[4];
    {
        float4 v = ((const float4*)(sig + (size_t)b * NN + (size_t)c * CHUNK))[t];
        int g = c * CHUNK + i0;
        r[0] = ((u64)f2ord(v.x) << 12) | (u64)(4095 - (g + 0));
        r[1] = ((u64)f2ord(v.y) << 12) | (u64)(4095 - (g + 1));
        r[2] = ((u64)f2ord(v.z) << 12) | (u64)(4095 - (g + 2));
        r[3] = ((u64)f2ord(v.w) << 12) | (u64)(4095 - (g + 3));
    }

    #pragma unroll
    for (int k = 2; k <= CHUNK; k <<= 1) {
        #pragma unroll
        for (int j = k >> 1; j > 0; j >>= 1) {
            if (j >= 128) {
                __syncthreads();
                #pragma unroll
                for (int e = 0; e < 4; e++) sm[i0 + e] = r[e];
                __syncthreads();
                bool desc     = ((i0 & k) == 0);
                bool lower    = ((i0 & j) == 0);
                bool keep_max = (desc == lower);
                #pragma unroll
                for (int e = 0; e < 4; e++) {
                    u64 o = sm[(i0 + e) ^ j];
                    r[e] = keep_max ? (r[e] > o ? r[e] : o)
                                    : (r[e] < o ? r[e] : o);
                }
            } else if (j >= 4) {
                int  m        = j >> 2;            // lane xor mask 1..16
                bool desc     = ((i0 & k) == 0);
                bool lower    = ((t & m) == 0);
                bool keep_max = (desc == lower);
                #pragma unroll
                for (int e = 0; e < 4; e++) {
                    u64 o = __shfl_xor_sync(0xffffffffu, r[e], m);
                    r[e] = keep_max ? (r[e] > o ? r[e] : o)
                                    : (r[e] < o ? r[e] : o);
                }
            } else if (j == 2) {
                cswap(r[0], r[2], ((i0 + 0) & k) == 0);
                cswap(r[1], r[3], ((i0 + 1) & k) == 0);
            } else {  // j == 1
                cswap(r[0], r[1], ((i0 + 0) & k) == 0);
                cswap(r[2], r[3], ((i0 + 2) & k) == 0);
            }
        }
    }

    u64* dst = g_scratch + (size_t)b * NN + (size_t)c * CHUNK + i0;
    #pragma unroll
    for (int e = 0; e < 4; e++) dst[e] = r[e];
}

// ---------------------------------------------------------------------------
// Kernel B: rank-based merge. CTA (b,c): thread t owns element t of sorted
// chunk c; rank = t + sum over other 3 chunks of count(key' > key), each a
// 10-step branchless binary search in smem (3-way ILP, no barriers).
// Ranks are a permutation of 0..4095; write idx iff rank < 1024.
// ---------------------------------------------------------------------------
__global__ __launch_bounds__(1024) void rank_merge_kernel() {
    __shared__ u64 sm[3 * CHUNK];
    const int b = blockIdx.x >> 2;
    const int c = blockIdx.x & 3;
    const int t = threadIdx.x;

    const u64* base = g_scratch + (size_t)b * NN;

    #pragma unroll
    for (int o = 0; o < 3; o++) {
        int oc = o + (o >= c ? 1 : 0);
        sm[o * CHUNK + t] = base[oc * CHUNK + t];
    }

    u64 key = base[c * CHUNK + t];
    __syncthreads();

    int c0 = 0, c1 = 0, c2 = 0;
    #pragma unroll
    for (int s = 512; s >= 1; s >>= 1) {
        if (sm[0 * CHUNK + c0 + s - 1] > key) c0 += s;
        if (sm[1 * CHUNK + c1 + s - 1] > key) c1 += s;
        if (sm[2 * CHUNK + c2 + s - 1] > key) c2 += s;
    }

    int rank = t + c0 + c1 + c2;
    if (rank < KK)
        g_topk[b * KK + rank] = 4095 - (int)(key & 0xFFFu);
}

// ---------------------------------------------------------------------------
// Gather (unchanged, measured 27.8us @ 5.2TB/s): 8 rows/CTA, 192 threads.
// ---------------------------------------------------------------------------
__global__ __launch_bounds__(192) void gather_kernel(const float4* __restrict__ x,
                                                     float4* __restrict__ out) {
    const int base = blockIdx.x * ROWS_PER_BLK;
    const int tid  = threadIdx.x;

    const float4* srcs[ROWS_PER_BLK];
    #pragma unroll
    for (int r = 0; r < ROWS_PER_BLK; r++) {
        int row = base + r;
        int b   = row / (KK + 1);
        int rr  = row - b * (KK + 1);
        int src_row = (rr == 0) ? 0 : (1 + g_topk[b * KK + rr - 1]);
        srcs[r] = x + ((size_t)b * (NN + 1) + (size_t)src_row) * (DD / 4);
    }

    float4 vals[ROWS_PER_BLK];
    #pragma unroll
    for (int r = 0; r < ROWS_PER_BLK; r++)
        vals[r] = __ldcs(srcs[r] + tid);

    #pragma unroll
    for (int r = 0; r < ROWS_PER_BLK; r++)
        out[(size_t)(base + r) * (DD / 4) + tid] = vals[r];
}

extern "C" void kernel_launch(void* const* d_in, const int* in_sizes, int n_in,
                              void* d_out, int out_size) {
    const float* x   = (const float*)d_in[0];   // [B, N+1, D] fp32
    const float* sig = (const float*)d_in[1];   // [B, N] fp32
    (void)in_sizes; (void)n_in; (void)out_size;

    sort_chunk_kernel<<<BB * NCHUNK, 256>>>(sig);
    rank_merge_kernel<<<BB * NCHUNK, 1024>>>();
    gather_kernel<<<BB * (KK + 1) / ROWS_PER_BLK, 192>>>((const float4*)x, (float4*)d_out);
}

// round 7
// speedup vs baseline: 2.0656x; 1.0154x over previous
#include <cuda_runtime.h>
#include <cstdint>

#define BB 32
#define NN 4096
#define DD 768
#define KK 1024
#define CHUNK 512
#define NCHUNK 8
#define ROWS_PER_BLK 8

typedef unsigned long long u64;

__device__ int g_topk[BB * KK];
__device__ u64 g_scratch[BB * NN];   // per-batch: 8 sorted descending chunks

// Map float to uint with ascending unsigned order == ascending float order.
__device__ __forceinline__ unsigned f2ord(float f) {
    unsigned u = __float_as_uint(f);
    return (u & 0x80000000u) ? ~u : (u | 0x80000000u);
}

__device__ __forceinline__ void cswap(u64& a, u64& b, bool desc) {
    bool sw = desc ? (a < b) : (a > b);
    if (sw) { u64 t = a; a = b; b = t; }
}

// ---------------------------------------------------------------------------
// Kernel A: CTA (b,c) sorts 512-element chunk c of batch b descending by
// composite key (ord << 12) | (4095 - global_idx) => jax.lax.top_k order
// (value desc, index asc). Keys strictly distinct.
// 128 threads x 4 keys; 45 stages fully unrolled:
//   j in {1,2}    : registers
//   j in {4..64}  : warp shfl_xor (mask j/4)
//   j in {128,256}: smem (only 3 stages)
// 256 CTAs => ~2 CTAs/SM on the 148-SM chip (2x round-5 occupancy).
// ---------------------------------------------------------------------------
__global__ __launch_bounds__(128) void sort_chunk_kernel(const float* __restrict__ sig) {
    __shared__ u64 sm[CHUNK];
    const int cta = blockIdx.x;
    const int b   = cta >> 3;
    const int c   = cta & 7;
    const int t   = threadIdx.x;
    const int i0  = 4 * t;

    u64 r[4];
    {
        float4 v = ((const float4*)(sig + (size_t)b * NN + (size_t)c * CHUNK))[t];
        int g = c * CHUNK + i0;
        r[0] = ((u64)f2ord(v.x) << 12) | (u64)(4095 - (g + 0));
        r[1] = ((u64)f2ord(v.y) << 12) | (u64)(4095 - (g + 1));
        r[2] = ((u64)f2ord(v.z) << 12) | (u64)(4095 - (g + 2));
        r[3] = ((u64)f2ord(v.w) << 12) | (u64)(4095 - (g + 3));
    }

    #pragma unroll
    for (int k = 2; k <= CHUNK; k <<= 1) {
        #pragma unroll
        for (int j = k >> 1; j > 0; j >>= 1) {
            if (j >= 128) {
                __syncthreads();
                #pragma unroll
                for (int e = 0; e < 4; e++) sm[i0 + e] = r[e];
                __syncthreads();
                bool desc     = ((i0 & k) == 0);   // k>=256: uniform over e
                bool lower    = ((i0 & j) == 0);
                bool keep_max = (desc == lower);
                #pragma unroll
                for (int e = 0; e < 4; e++) {
                    u64 o = sm[(i0 + e) ^ j];
                    r[e] = keep_max ? (r[e] > o ? r[e] : o)
                                    : (r[e] < o ? r[e] : o);
                }
            } else if (j >= 4) {
                int  m        = j >> 2;            // lane xor mask 1..16
                bool desc     = ((i0 & k) == 0);   // k>=8: uniform over e
                bool lower    = ((t & m) == 0);
                bool keep_max = (desc == lower);
                #pragma unroll
                for (int e = 0; e < 4; e++) {
                    u64 o = __shfl_xor_sync(0xffffffffu, r[e], m);
                    r[e] = keep_max ? (r[e] > o ? r[e] : o)
                                    : (r[e] < o ? r[e] : o);
                }
            } else if (j == 2) {
                cswap(r[0], r[2], ((i0 + 0) & k) == 0);
                cswap(r[1], r[3], ((i0 + 1) & k) == 0);
            } else {  // j == 1
                cswap(r[0], r[1], ((i0 + 0) & k) == 0);
                cswap(r[2], r[3], ((i0 + 2) & k) == 0);
            }
        }
    }

    u64* dst = g_scratch + (size_t)b * NN + (size_t)c * CHUNK + i0;
    #pragma unroll
    for (int e = 0; e < 4; e++) dst[e] = r[e];
}

// ---------------------------------------------------------------------------
// Kernel B: rank-based merge. CTA (b,c): thread t owns element t of sorted
// chunk c; rank = t + sum over the other 7 chunks of count(key' > key), each
// a 9-step branchless binary search in smem (7-way ILP, no barriers after
// load). Ranks are a permutation of 0..4095; write idx iff rank < 1024.
// ---------------------------------------------------------------------------
__global__ __launch_bounds__(512) void rank_merge_kernel() {
    __shared__ u64 sm[(NCHUNK - 1) * CHUNK];   // 7 x 512 keys = 28 KB
    const int b = blockIdx.x >> 3;
    const int c = blockIdx.x & 7;
    const int t = threadIdx.x;

    const u64* base = g_scratch + (size_t)b * NN;

    #pragma unroll
    for (int o = 0; o < NCHUNK - 1; o++) {
        int oc = o + (o >= c ? 1 : 0);
        sm[o * CHUNK + t] = base[oc * CHUNK + t];
    }

    u64 key = base[c * CHUNK + t];
    __syncthreads();

    int cnt[NCHUNK - 1];
    #pragma unroll
    for (int o = 0; o < NCHUNK - 1; o++) cnt[o] = 0;

    #pragma unroll
    for (int s = CHUNK / 2; s >= 1; s >>= 1) {
        #pragma unroll
        for (int o = 0; o < NCHUNK - 1; o++) {
            if (sm[o * CHUNK + cnt[o] + s - 1] > key) cnt[o] += s;
        }
    }

    int rank = t;
    #pragma unroll
    for (int o = 0; o < NCHUNK - 1; o++) rank += cnt[o];

    if (rank < KK)
        g_topk[b * KK + rank] = 4095 - (int)(key & 0xFFFu);
}

// ---------------------------------------------------------------------------
// Gather (unchanged, measured 27.8us @ 5.2TB/s): 8 rows/CTA, 192 threads.
// ---------------------------------------------------------------------------
__global__ __launch_bounds__(192) void gather_kernel(const float4* __restrict__ x,
                                                     float4* __restrict__ out) {
    const int base = blockIdx.x * ROWS_PER_BLK;
    const int tid  = threadIdx.x;

    const float4* srcs[ROWS_PER_BLK];
    #pragma unroll
    for (int r = 0; r < ROWS_PER_BLK; r++) {
        int row = base + r;
        int b   = row / (KK + 1);
        int rr  = row - b * (KK + 1);
        int src_row = (rr == 0) ? 0 : (1 + g_topk[b * KK + rr - 1]);
        srcs[r] = x + ((size_t)b * (NN + 1) + (size_t)src_row) * (DD / 4);
    }

    float4 vals[ROWS_PER_BLK];
    #pragma unroll
    for (int r = 0; r < ROWS_PER_BLK; r++)
        vals[r] = __ldcs(srcs[r] + tid);

    #pragma unroll
    for (int r = 0; r < ROWS_PER_BLK; r++)
        out[(size_t)(base + r) * (DD / 4) + tid] = vals[r];
}

extern "C" void kernel_launch(void* const* d_in, const int* in_sizes, int n_in,
                              void* d_out, int out_size) {
    const float* x   = (const float*)d_in[0];   // [B, N+1, D] fp32
    const float* sig = (const float*)d_in[1];   // [B, N] fp32
    (void)in_sizes; (void)n_in; (void)out_size;

    sort_chunk_kernel<<<BB * NCHUNK, 128>>>(sig);
    rank_merge_kernel<<<BB * NCHUNK, 512>>>();
    gather_kernel<<<BB * (KK + 1) / ROWS_PER_BLK, 192>>>((const float4*)x, (float4*)d_out);
}

// round 8
// speedup vs baseline: 2.1385x; 1.0353x over previous
#include <cuda_runtime.h>
#include <cstdint>

#define BB 32
#define NN 4096
#define DD 768
#define KK 1024
#define CHUNK 512
#define NCHUNK 8
#define ROWS_PER_BLK 8

typedef unsigned long long u64;

__device__ int g_topk[BB * KK];
__device__ u64 g_scratch[BB * NN];   // per-batch: 8 sorted descending chunks

// Map float to uint with ascending unsigned order == ascending float order.
__device__ __forceinline__ unsigned f2ord(float f) {
    unsigned u = __float_as_uint(f);
    return (u & 0x80000000u) ? ~u : (u | 0x80000000u);
}

// ---------------------------------------------------------------------------
// Kernel A: CTA (b,c) sorts 512-element chunk c of batch b descending by
// composite key (ord << 12) | (4095 - global_idx) => jax.lax.top_k order
// (value desc, index asc). Keys strictly distinct.
// ONE key per thread, 512 threads: grid = 256 CTAs x 16 warps = 4096 warps
// (~27/SM) for latency hiding. 45 stages fully unrolled:
//   j in {1..16}   : warp shfl_xor           (35 stages)
//   j in {32..256} : smem exchange + barrier (10 stages)
// ---------------------------------------------------------------------------
__global__ __launch_bounds__(512) void sort_chunk_kernel(const float* __restrict__ sig) {
    __shared__ u64 sm[CHUNK];
    const int b = blockIdx.x >> 3;
    const int c = blockIdx.x & 7;
    const int t = threadIdx.x;

    const int g = c * CHUNK + t;
    float v = sig[(size_t)b * NN + g];
    u64 r = ((u64)f2ord(v) << 12) | (u64)(4095 - g);

    #pragma unroll
    for (int k = 2; k <= CHUNK; k <<= 1) {
        #pragma unroll
        for (int j = k >> 1; j > 0; j >>= 1) {
            // descending overall: keep max at lower index when (t&k)==0
            bool keep_max = (((t & k) == 0) == ((t & j) == 0));
            u64 o;
            if (j >= 32) {
                __syncthreads();
                sm[t] = r;
                __syncthreads();
                o = sm[t ^ j];
            } else {
                o = __shfl_xor_sync(0xffffffffu, r, j);
            }
            r = keep_max ? (r > o ? r : o) : (r < o ? r : o);
        }
    }

    g_scratch[(size_t)b * NN + g] = r;
}

// ---------------------------------------------------------------------------
// Kernel B: rank-based merge. CTA (b,c): thread t owns element t of sorted
// chunk c; rank = t + sum over the other 7 chunks of count(key' > key), each
// a 9-step branchless binary search in smem (7-way ILP, no barriers after
// load). Ranks are a permutation of 0..4095; write idx iff rank < 1024.
// ---------------------------------------------------------------------------
__global__ __launch_bounds__(512) void rank_merge_kernel() {
    __shared__ u64 sm[(NCHUNK - 1) * CHUNK];   // 7 x 512 keys = 28 KB
    const int b = blockIdx.x >> 3;
    const int c = blockIdx.x & 7;
    const int t = threadIdx.x;

    const u64* base = g_scratch + (size_t)b * NN;

    #pragma unroll
    for (int o = 0; o < NCHUNK - 1; o++) {
        int oc = o + (o >= c ? 1 : 0);
        sm[o * CHUNK + t] = base[oc * CHUNK + t];
    }

    u64 key = base[c * CHUNK + t];
    __syncthreads();

    int cnt[NCHUNK - 1];
    #pragma unroll
    for (int o = 0; o < NCHUNK - 1; o++) cnt[o] = 0;

    #pragma unroll
    for (int s = CHUNK / 2; s >= 1; s >>= 1) {
        #pragma unroll
        for (int o = 0; o < NCHUNK - 1; o++) {
            if (sm[o * CHUNK + cnt[o] + s - 1] > key) cnt[o] += s;
        }
    }

    int rank = t;
    #pragma unroll
    for (int o = 0; o < NCHUNK - 1; o++) rank += cnt[o];

    if (rank < KK)
        g_topk[b * KK + rank] = 4095 - (int)(key & 0xFFFu);
}

// ---------------------------------------------------------------------------
// Gather (unchanged, measured 27.8us @ 5.2TB/s): 8 rows/CTA, 192 threads.
// ---------------------------------------------------------------------------
__global__ __launch_bounds__(192) void gather_kernel(const float4* __restrict__ x,
                                                     float4* __restrict__ out) {
    const int base = blockIdx.x * ROWS_PER_BLK;
    const int tid  = threadIdx.x;

    const float4* srcs[ROWS_PER_BLK];
    #pragma unroll
    for (int r = 0; r < ROWS_PER_BLK; r++) {
        int row = base + r;
        int b   = row / (KK + 1);
        int rr  = row - b * (KK + 1);
        int src_row = (rr == 0) ? 0 : (1 + g_topk[b * KK + rr - 1]);
        srcs[r] = x + ((size_t)b * (NN + 1) + (size_t)src_row) * (DD / 4);
    }

    float4 vals[ROWS_PER_BLK];
    #pragma unroll
    for (int r = 0; r < ROWS_PER_BLK; r++)
        vals[r] = __ldcs(srcs[r] + tid);

    #pragma unroll
    for (int r = 0; r < ROWS_PER_BLK; r++)
        out[(size_t)(base + r) * (DD / 4) + tid] = vals[r];
}

extern "C" void kernel_launch(void* const* d_in, const int* in_sizes, int n_in,
                              void* d_out, int out_size) {
    const float* x   = (const float*)d_in[0];   // [B, N+1, D] fp32
    const float* sig = (const float*)d_in[1];   // [B, N] fp32
    (void)in_sizes; (void)n_in; (void)out_size;

    sort_chunk_kernel<<<BB * NCHUNK, CHUNK>>>(sig);
    rank_merge_kernel<<<BB * NCHUNK, CHUNK>>>();
    gather_kernel<<<BB * (KK + 1) / ROWS_PER_BLK, 192>>>((const float4*)x, (float4*)d_out);
}